// round 7
// baseline (speedup 1.0000x reference)
#include <cuda_runtime.h>
#include <cuda_bf16.h>
#include <math.h>
#include <float.h>
#include <stdint.h>

// ---------------------------------------------------------------- constants
#define D        256
#define NC       1024
#define NF       8192
#define NTOT     9216
#define TM       128          // rows per CTA
#define TN       128          // embeddings per tile
#define KSTEPS   8            // 256 / 32 (int8 K per mma)
#define SXB      272          // row stride: 256 int8 + 4B fp32 e2 + 12 pad
#define TILE_B   (TM * SXB)   // 34816 bytes per tile
#define NTHR     512
#define NWARP    16
#define QSCALE   24.0f

#define QOFF      1
#define FPERP_OFF 12632065
#define CPERP_OFF 12632066
#define ENC_OFF   12632067

// dynamic smem layout (bytes): X + 3 E buffers + mbarriers
#define SM_X      0
#define SM_E0     TILE_B
#define SM_MBAR   (4 * TILE_B)        // 139264
#define SM_TOTAL  (4 * TILE_B + 64)   // 139328

__device__ int    g_counts[NTOT];
__device__ double g_loss[2];
__device__ __align__(16) float g_e2[NTOT];
// quantized embeddings: row stride 272B = 256 int8 + fp32 e2 @ +256 + pad
__device__ __align__(128) unsigned char g_e8[(size_t)NTOT * SXB];

// ---------------------------------------------------------------- helpers
static __device__ __forceinline__ uint32_t smem_u32(const void* p) {
    uint32_t a;
    asm("{ .reg .u64 t; cvta.to.shared.u64 t, %1; cvt.u32.u64 %0, t; }"
        : "=r"(a) : "l"(p));
    return a;
}
static __device__ __forceinline__ int q8(float v) {
    return __float2int_rn(fminf(fmaxf(v * QSCALE, -127.f), 127.f));
}
static __device__ __forceinline__ uint32_t pk4(float a, float b, float c, float d) {
    return (uint32_t)(q8(a) & 0xff) | ((uint32_t)(q8(b) & 0xff) << 8)
         | ((uint32_t)(q8(c) & 0xff) << 16) | ((uint32_t)(q8(d) & 0xff) << 24);
}
static __device__ __forceinline__ bool dlt(float da, int ia, float db, int ib) {
    return (da < db) || (da == db && ia < ib);
}
static __device__ __forceinline__ void ins3(float d, int i,
        float& d0, int& i0, float& d1, int& i1, float& d2, int& i2) {
    if (dlt(d, i, d2, i2)) {
        if (dlt(d, i, d1, i1)) {
            d2 = d1; i2 = i1;
            if (dlt(d, i, d0, i0)) { d1 = d0; i1 = i0; d0 = d; i0 = i; }
            else                    { d1 = d;  i1 = i; }
        } else { d2 = d; i2 = i; }
    }
}

#define LDSM4(r, addr) \
    asm volatile("ldmatrix.sync.aligned.m8n8.x4.shared.b16 {%0,%1,%2,%3}, [%4];" \
        : "=r"((r)[0]), "=r"((r)[1]), "=r"((r)[2]), "=r"((r)[3]) : "r"(addr))

#define MMAI8(c, a, b0_, b1_) \
    asm volatile("mma.sync.aligned.m16n8k32.row.col.s32.s8.s8.s32 " \
        "{%0,%1,%2,%3}, {%4,%5,%6,%7}, {%8,%9}, {%0,%1,%2,%3};" \
        : "+r"((c)[0]), "+r"((c)[1]), "+r"((c)[2]), "+r"((c)[3]) \
        : "r"((a)[0]), "r"((a)[1]), "r"((a)[2]), "r"((a)[3]), \
          "r"(b0_), "r"(b1_))

#define MBAR_INIT(a, n) \
    asm volatile("mbarrier.init.shared.b64 [%0], %1;" :: "r"(a), "r"(n) : "memory")
#define MBAR_EXPECT_TX(a, bytes) \
    asm volatile("mbarrier.arrive.expect_tx.shared.b64 _, [%0], %1;" \
                 :: "r"(a), "r"(bytes) : "memory")
#define BULK_CP(dst, src, bytes, mbar) \
    asm volatile("cp.async.bulk.shared::cluster.global.mbarrier::complete_tx::bytes " \
                 "[%0], [%1], %2, [%3];" \
                 :: "r"(dst), "l"(src), "r"(bytes), "r"(mbar) : "memory")
#define MBAR_WAIT(a, par) do {                                               \
    uint32_t _m = (a), _p = (par), _d;                                       \
    asm volatile("{\n\t.reg .pred p;\n\t"                                    \
        "mbarrier.try_wait.parity.acquire.cta.shared::cta.b64 p, [%1], %2;\n\t" \
        "selp.b32 %0, 1, 0, p;\n\t}" : "=r"(_d) : "r"(_m), "r"(_p) : "memory"); \
    if (!_d) {                                                               \
        asm volatile("{\n\t.reg .pred P1;\n\tWL%=: \n\t"                     \
            "mbarrier.try_wait.parity.acquire.cta.shared::cta.b64 P1, [%0], %1, 0x989680;\n\t" \
            "@P1 bra.uni WD%=;\n\tbra.uni WL%=;\n\tWD%=: \n\t}"              \
            :: "r"(_m), "r"(_p) : "memory");                                 \
    }                                                                        \
} while (0)

// ---------------------------------------------------------------- small kernels
__global__ void vq_zero() {
    int i = blockIdx.x * 256 + threadIdx.x;   // 36*256 = 9216
    g_counts[i] = 0;
    if (i < 2) g_loss[i] = 0.0;
}

__global__ void vq_e2(const float* __restrict__ Ec, const float* __restrict__ Ef) {
    int gw   = (blockIdx.x * blockDim.x + threadIdx.x) >> 5;
    int lane = threadIdx.x & 31;
    if (gw >= NTOT) return;
    const float* row = (gw < NC) ? (Ec + (size_t)gw * D)
                                 : (Ef + (size_t)(gw - NC) * D);
    const float4* r4 = (const float4*)row;
    float4 a = r4[lane];
    float4 b = r4[lane + 32];
    float s = a.x*a.x + a.y*a.y + a.z*a.z + a.w*a.w
            + b.x*b.x + b.y*b.y + b.z*b.z + b.w*b.w;
    #pragma unroll
    for (int o = 16; o > 0; o >>= 1) s += __shfl_xor_sync(0xffffffffu, s, o);
    if (lane == 0) g_e2[gw] = s;
}

// build quantized embedding matrix: 256 s8 + fp32 e2 per 272B row
__global__ void vq_cvt(const float* __restrict__ Ec, const float* __restrict__ Ef) {
    int idx = blockIdx.x * 256 + threadIdx.x;   // 612*256 = 156672 = 9216*17
    int row = idx / 17;
    int ch  = idx - row * 17;                   // 16B chunk within 272B row
    uint4 pv = make_uint4(0u, 0u, 0u, 0u);
    if (ch < 16) {
        const float* src = (row < NC) ? (Ec + (size_t)row * D + ch * 16)
                                      : (Ef + (size_t)(row - NC) * D + ch * 16);
        const float4* s4 = (const float4*)src;
        float4 a = s4[0], b = s4[1], c = s4[2], d = s4[3];
        pv.x = pk4(a.x, a.y, a.z, a.w);
        pv.y = pk4(b.x, b.y, b.z, b.w);
        pv.z = pk4(c.x, c.y, c.z, c.w);
        pv.w = pk4(d.x, d.y, d.z, d.w);
    } else {
        pv.x = __float_as_uint(g_e2[row]);      // fp32 e2 at byte 256
    }
    *(uint4*)(g_e8 + (size_t)row * SXB + ch * 16) = pv;
}

// ---------------------------------------------------------------- main kernel
__global__ void __launch_bounds__(NTHR, 1) vq_main(
        const float* __restrict__ feats,
        const float* __restrict__ Ec,
        const float* __restrict__ Ef,
        float* __restrict__ out)
{
    extern __shared__ char smc[];
    const uint32_t sbase = smem_u32(smc);
    const int tid  = threadIdx.x;
    const int wid  = tid >> 5;
    const int lane = tid & 31;
    const int wm   = wid & 3;       // warp row group (4 x 32 rows)
    const int wn   = wid >> 2;      // warp col group (4 x 32 embs)
    const int g8   = lane >> 2;     // 0..7
    const int tid4 = lane & 3;

    // role of this CTA
    const float* Xf; int ntiles, gbase_e, valid, gbase, lslot;
    if (blockIdx.x == 0) {
        Xf = feats;                 ntiles = NC / TN;  gbase_e = 0;
        valid = 64;  gbase = 0;     lslot = 0;
    } else {
        int b = blockIdx.x - 1;
        Xf = feats + (size_t)(64 + b * TM) * D;
        ntiles = NF / TN;  gbase_e = NC;
        valid = TM;  gbase = 64 + b * TM;  lslot = 1;
    }

    const uint32_t mbar = sbase + SM_MBAR;      // 3 mbarriers, 8B apart

    if (tid == 0) {
        MBAR_INIT(mbar + 0, 1);
        MBAR_INIT(mbar + 8, 1);
        MBAR_INIT(mbar + 16, 1);
    }
    __syncthreads();

    // prologue: bulk-load tiles 0,1,2 (ntiles >= 8 always)
    if (tid == 0) {
        #pragma unroll
        for (int s = 0; s < 3; s++) {
            MBAR_EXPECT_TX(mbar + 8 * s, TILE_B);
            BULK_CP(sbase + SM_E0 + s * TILE_B,
                    g_e8 + (size_t)(gbase_e + s * TN) * SXB, TILE_B, mbar + 8 * s);
        }
    }

    // convert X block to int8 smem (pad rows -> 0)
    for (int q = tid; q < TM * 16; q += NTHR) {   // 2048 16B chunks
        int row = q >> 4, ch = q & 15;
        uint4 pv = make_uint4(0u, 0u, 0u, 0u);
        if (row < valid) {
            const float4* xs = (const float4*)(Xf + (size_t)row * D + ch * 16);
            float4 a = xs[0], b = xs[1], c = xs[2], d = xs[3];
            pv.x = pk4(a.x, a.y, a.z, a.w);
            pv.y = pk4(b.x, b.y, b.z, b.w);
            pv.z = pk4(c.x, c.y, c.z, c.w);
            pv.w = pk4(d.x, d.y, d.z, d.w);
        }
        *(uint4*)(smc + SM_X + row * SXB + ch * 16) = pv;
    }
    __syncthreads();

    // ldmatrix per-thread offsets (16B chunks of int8)
    const int arow  = wm * 32 + (lane & 7) + ((lane >> 3) & 1) * 8;
    const uint32_t aoff0 = (uint32_t)(arow * SXB + (lane >> 4) * 16);
    const uint32_t aoff1 = aoff0 + 16 * SXB;
    const int brow  = (lane & 7) + ((lane >> 4) & 1) * 8;
    const uint32_t boff0 = (uint32_t)((wn * 32 + brow) * SXB + ((lane >> 3) & 1) * 16);
    const uint32_t boff1 = boff0 + 16 * SXB;

    // per-thread approx top-3 per owned row (4 rows: wm*32 + g8 + li*8)
    float td[4][3]; int ti[4][3];
    #pragma unroll
    for (int li = 0; li < 4; li++)
        #pragma unroll
        for (int q = 0; q < 3; q++) { td[li][q] = FLT_MAX; ti[li][q] = 0x7fffffff; }

    const uint32_t xb = sbase + SM_X;
    const float c2 = -2.0f / (QSCALE * QSCALE);

    // ---------------- main tile loop ----------------------------------------
    for (int t = 0; t < ntiles; t++) {
        const int slot = t % 3;
        MBAR_WAIT(mbar + 8 * slot, (uint32_t)((t / 3) & 1));

        const uint32_t eb  = sbase + SM_E0 + slot * TILE_B;
        const char*    ebp = smc + SM_E0 + slot * TILE_B;

        int acc[2][4][4];
        #pragma unroll
        for (int mt = 0; mt < 2; mt++)
            #pragma unroll
            for (int nt = 0; nt < 4; nt++)
                #pragma unroll
                for (int q = 0; q < 4; q++) acc[mt][nt][q] = 0;

        // software-pipelined fragment loop: 32 int8 K per step
        uint32_t af[2][2][4], bf[2][2][4];
        LDSM4(af[0][0], xb + aoff0);
        LDSM4(af[0][1], xb + aoff1);
        LDSM4(bf[0][0], eb + boff0);
        LDSM4(bf[0][1], eb + boff1);
        #pragma unroll
        for (int ks = 0; ks < KSTEPS; ks++) {
            const int cur = ks & 1, nxt = cur ^ 1;
            if (ks < KSTEPS - 1) {
                const uint32_t kb = (ks + 1) * 32;
                LDSM4(af[nxt][0], xb + aoff0 + kb);
                LDSM4(af[nxt][1], xb + aoff1 + kb);
                LDSM4(bf[nxt][0], eb + boff0 + kb);
                LDSM4(bf[nxt][1], eb + boff1 + kb);
            }
            #pragma unroll
            for (int np = 0; np < 2; np++) {
                MMAI8(acc[0][2*np],     af[cur][0], bf[cur][np][0], bf[cur][np][1]);
                MMAI8(acc[1][2*np],     af[cur][1], bf[cur][np][0], bf[cur][np][1]);
                MMAI8(acc[0][2*np + 1], af[cur][0], bf[cur][np][2], bf[cur][np][3]);
                MMAI8(acc[1][2*np + 1], af[cur][1], bf[cur][np][2], bf[cur][np][3]);
            }
        }

        // scores: e2 - (2/s^2)*idot ; update per-thread top-3 lists
        const int ebase = gbase_e + t * TN;
        #pragma unroll
        for (int mt = 0; mt < 2; mt++) {
            #pragma unroll
            for (int nt = 0; nt < 4; nt++) {
                int n  = wn * 32 + nt * 8 + tid4 * 2;
                float e2a = *(const float*)(ebp + n * SXB + 256);
                float e2c = *(const float*)(ebp + (n + 1) * SXB + 256);
                int ge = ebase + n;
                float s0 = fmaf(c2, (float)acc[mt][nt][0], e2a);
                float s1 = fmaf(c2, (float)acc[mt][nt][1], e2c);
                float s2 = fmaf(c2, (float)acc[mt][nt][2], e2a);
                float s3 = fmaf(c2, (float)acc[mt][nt][3], e2c);
                int l0 = mt * 2, l1 = mt * 2 + 1;
                ins3(s0, ge,     td[l0][0], ti[l0][0], td[l0][1], ti[l0][1], td[l0][2], ti[l0][2]);
                ins3(s1, ge + 1, td[l0][0], ti[l0][0], td[l0][1], ti[l0][1], td[l0][2], ti[l0][2]);
                ins3(s2, ge,     td[l1][0], ti[l1][0], td[l1][1], ti[l1][1], td[l1][2], ti[l1][2]);
                ins3(s3, ge + 1, td[l1][0], ti[l1][0], td[l1][1], ti[l1][1], td[l1][2], ti[l1][2]);
            }
        }
        __syncthreads();   // everyone done reading this buffer

        if (t + 3 < ntiles && tid == 0) {
            MBAR_EXPECT_TX(mbar + 8 * slot, TILE_B);
            BULK_CP(sbase + SM_E0 + slot * TILE_B,
                    g_e8 + (size_t)(gbase_e + (t + 3) * TN) * SXB,
                    TILE_B, mbar + 8 * slot);
        }
    }

    // ---------------- merge: 16 threads x top3 -> 48 cands per row -----------
    float* cd  = (float*)smc;                    // [128][48] floats
    int*   ci  = (int*)(smc + 24576);            // [128][48] ints
    float* cd8 = (float*)(smc + 49152);          // [128][8]
    int*   ci8 = (int*)(smc + 53248);            // [128][8]
    int*   sel = (int*)(smc + 57344);            // [128][3]

    const int slot2 = wn * 4 + tid4;             // 0..15 per row
    #pragma unroll
    for (int li = 0; li < 4; li++) {
        int row = wm * 32 + g8 + li * 8;
        #pragma unroll
        for (int q = 0; q < 3; q++) {
            cd[row * 48 + slot2 * 3 + q] = td[li][q];
            ci[row * 48 + slot2 * 3 + q] = ti[li][q];
        }
    }
    __syncthreads();

    // approx top-8 of 48 (selection with tie-break; destructive)
    if (tid < valid) {
        for (int s = 0; s < 8; s++) {
            float bd = FLT_MAX; int bi = 0x7fffffff; int bj = -1;
            for (int j = 0; j < 48; j++) {
                float dv = cd[tid * 48 + j]; int iv = ci[tid * 48 + j];
                if (dlt(dv, iv, bd, bi)) { bd = dv; bi = iv; bj = j; }
            }
            cd[tid * 48 + bj] = FLT_MAX; ci[tid * 48 + bj] = 0x7fffffff;
            cd8[tid * 8 + s] = bd;  ci8[tid * 8 + s] = bi;
        }
    }
    __syncthreads();

    // ---------------- exact fp32 rescore of 8 candidates per row ------------
    for (int it = wid; it < valid * 8; it += NWARP) {
        int row = it >> 3, c = it & 7;
        int idx = ci8[row * 8 + c];
        const float* erow = (idx < NC) ? (Ec + (size_t)idx * D)
                                       : (Ef + (size_t)(idx - NC) * D);
        const float4* e4 = (const float4*)erow;
        const float4* x4 = (const float4*)(Xf + (size_t)row * D);
        float4 ea = e4[lane * 2], ebv = e4[lane * 2 + 1];
        float4 xa = x4[lane * 2], xbv = x4[lane * 2 + 1];
        float dot = ea.x*xa.x + ea.y*xa.y + ea.z*xa.z + ea.w*xa.w
                  + ebv.x*xbv.x + ebv.y*xbv.y + ebv.z*xbv.z + ebv.w*xbv.w;
        #pragma unroll
        for (int o = 16; o > 0; o >>= 1) dot += __shfl_xor_sync(0xffffffffu, dot, o);
        if (lane == 0) cd8[row * 8 + c] = g_e2[idx] - 2.f * dot;
    }
    __syncthreads();

    // exact top-3 with index tie-break (matches lax.top_k stability)
    if (tid < valid) {
        float d0 = FLT_MAX, d1 = FLT_MAX, d2 = FLT_MAX;
        int   i0 = 0x7fffffff, i1 = 0x7fffffff, i2 = 0x7fffffff;
        #pragma unroll
        for (int s = 0; s < 8; s++)
            ins3(cd8[tid * 8 + s], ci8[tid * 8 + s], d0, i0, d1, i1, d2, i2);
        sel[tid * 3 + 0] = i0;
        sel[tid * 3 + 1] = i1;
        sel[tid * 3 + 2] = i2;
    }
    __syncthreads();

    // ---------------- gather + write quantized/indices + loss + counts ------
    float lsum = 0.f;
    for (int j = wid; j < valid * 3; j += NWARP) {
        int r  = j / 3;
        int kk = j - r * 3;
        int idx = sel[j];
        int g  = gbase + r;
        const float* erow = (idx < NC) ? (Ec + (size_t)idx * D)
                                       : (Ef + (size_t)(idx - NC) * D);
        const float4* e4 = (const float4*)erow;
        const float4* x4 = (const float4*)(Xf + (size_t)r * D);
        float4 v0 = e4[lane * 2], v1 = e4[lane * 2 + 1];
        float4 x0 = x4[lane * 2], x1 = x4[lane * 2 + 1];
        size_t qb = QOFF + ((size_t)g * 3 + kk) * D + lane * 8;
        out[qb + 0] = v0.x; out[qb + 1] = v0.y; out[qb + 2] = v0.z; out[qb + 3] = v0.w;
        out[qb + 4] = v1.x; out[qb + 5] = v1.y; out[qb + 6] = v1.z; out[qb + 7] = v1.w;
        float dx;
        dx = v0.x - x0.x; lsum += dx * dx;
        dx = v0.y - x0.y; lsum += dx * dx;
        dx = v0.z - x0.z; lsum += dx * dx;
        dx = v0.w - x0.w; lsum += dx * dx;
        dx = v1.x - x1.x; lsum += dx * dx;
        dx = v1.y - x1.y; lsum += dx * dx;
        dx = v1.z - x1.z; lsum += dx * dx;
        dx = v1.w - x1.w; lsum += dx * dx;
        if (lane == 0) {
            out[ENC_OFF + (size_t)g * 3 + kk] = (float)idx;
            atomicAdd(&g_counts[idx], 1);
        }
    }
    #pragma unroll
    for (int o = 16; o > 0; o >>= 1) lsum += __shfl_xor_sync(0xffffffffu, lsum, o);
    if (lane == 0) atomicAdd(&g_loss[lslot], (double)lsum);
}

// ---------------------------------------------------------------- finalize
__global__ void vq_finalize(float* __restrict__ out) {
    int tid = threadIdx.x;                    // 1024 threads
    float hf = 0.f;
    for (int i = tid; i < NF; i += 1024) {
        float avg = (float)g_counts[NC + i] * (1.0f / 16384.0f);
        hf += avg * logf(avg + 1e-10f);
    }
    float avgc = (float)g_counts[tid] * (1.0f / 64.0f);
    float hc = avgc * logf(avgc + 1e-10f);

    __shared__ float redf[32], redc[32];
    int lane = tid & 31, w = tid >> 5;
    #pragma unroll
    for (int o = 16; o > 0; o >>= 1) {
        hf += __shfl_xor_sync(0xffffffffu, hf, o);
        hc += __shfl_xor_sync(0xffffffffu, hc, o);
    }
    if (lane == 0) { redf[w] = hf; redc[w] = hc; }
    __syncthreads();
    if (tid < 32) {
        float f = redf[tid], c = redc[tid];
        #pragma unroll
        for (int o = 16; o > 0; o >>= 1) {
            f += __shfl_xor_sync(0xffffffffu, f, o);
            c += __shfl_xor_sync(0xffffffffu, c, o);
        }
        if (tid == 0) {
            out[FPERP_OFF] = expf(-f);
            out[CPERP_OFF] = expf(-c);
            out[0] = (float)(1.25 * (g_loss[0] / (64.0 * 3.0 * 256.0)
                                   + g_loss[1] / (16384.0 * 3.0 * 256.0)));
        }
    }
}

// ---------------------------------------------------------------- launcher
extern "C" void kernel_launch(void* const* d_in, const int* in_sizes, int n_in,
                              void* d_out, int out_size) {
    (void)in_sizes; (void)n_in; (void)out_size;
    const float* feats = (const float*)d_in[0];
    const float* Ec    = (const float*)d_in[1];
    const float* Ef    = (const float*)d_in[2];
    float* out = (float*)d_out;

    cudaFuncSetAttribute(vq_main, cudaFuncAttributeMaxDynamicSharedMemorySize, SM_TOTAL);

    vq_zero<<<36, 256>>>();
    vq_e2<<<NTOT / 8, 256>>>(Ec, Ef);
    vq_cvt<<<612, 256>>>(Ec, Ef);
    vq_main<<<129, NTHR, SM_TOTAL>>>(feats, Ec, Ef, out);
    vq_finalize<<<1, 1024>>>(out);
}

// round 8
// speedup vs baseline: 2.4262x; 2.4262x over previous
#include <cuda_runtime.h>
#include <cuda_bf16.h>
#include <math.h>
#include <float.h>
#include <stdint.h>

// ---------------------------------------------------------------- constants
#define D        256
#define NC       1024
#define NF       8192
#define NTOT     9216
#define TM       128          // rows per CTA
#define TN       128          // embeddings per tile
#define KSTEPS   17           // 272 aug cols / 16
#define SXB      560          // row stride bytes: 280 bf16 (272 aug + 8 pad)
#define TILE_B   (TM * SXB)   // 71680 bytes per tile
#define NTHR     512
#define NWARP    16

#define QOFF      1
#define FPERP_OFF 12632065
#define CPERP_OFF 12632066
#define ENC_OFF   12632067

// dynamic smem layout (bytes)
#define SM_X      0
#define SM_E0     TILE_B              // 71680
#define SM_E1     (2 * TILE_B)        // 143360
#define SM_MBAR   (3 * TILE_B)        // 215040: full0,full1,empty0,empty1 (8B each)
#define SM_TOTAL  (3 * TILE_B + 64)   // 215104

__device__ int    g_counts[NTOT];
__device__ double g_loss[2];
__device__ __align__(16) float g_e2[NTOT];
// pre-padded, K-augmented bf16 embeddings: row stride 560B, cols 0..255 data,
// col 256 = -e2/2, cols 257..279 = 0
__device__ __align__(128) unsigned char g_ebf[(size_t)NTOT * SXB];

// ---------------------------------------------------------------- helpers
static __device__ __forceinline__ uint32_t smem_u32(const void* p) {
    uint32_t a;
    asm("{ .reg .u64 t; cvta.to.shared.u64 t, %1; cvt.u32.u64 %0, t; }"
        : "=r"(a) : "l"(p));
    return a;
}
static __device__ __forceinline__ uint32_t pk(float lo, float hi) {
    uint32_t r;
    asm("cvt.rn.bf16x2.f32 %0, %1, %2;" : "=r"(r) : "f"(hi), "f"(lo));
    return r;
}
static __device__ __forceinline__ bool dlt(float da, int ia, float db, int ib) {
    return (da < db) || (da == db && ia < ib);
}
// hot-loop insertion: float-only compare (no tie-break; exact ties between
// distinct embeddings' approx scores do not occur; final order fixed by rescore)
static __device__ __forceinline__ void ins3f(float s, int i,
        float& d0, int& i0, float& d1, int& i1, float& d2, int& i2) {
    if (s < d2) {
        if (s < d1) {
            d2 = d1; i2 = i1;
            if (s < d0) { d1 = d0; i1 = i0; d0 = s; i0 = i; }
            else         { d1 = s;  i1 = i; }
        } else { d2 = s; i2 = i; }
    }
}
static __device__ __forceinline__ void ins3(float d, int i,
        float& d0, int& i0, float& d1, int& i1, float& d2, int& i2) {
    if (dlt(d, i, d2, i2)) {
        if (dlt(d, i, d1, i1)) {
            d2 = d1; i2 = i1;
            if (dlt(d, i, d0, i0)) { d1 = d0; i1 = i0; d0 = d; i0 = i; }
            else                    { d1 = d;  i1 = i; }
        } else { d2 = d; i2 = i; }
    }
}

#define LDSM4(r, addr) \
    asm volatile("ldmatrix.sync.aligned.m8n8.x4.shared.b16 {%0,%1,%2,%3}, [%4];" \
        : "=r"((r)[0]), "=r"((r)[1]), "=r"((r)[2]), "=r"((r)[3]) : "r"(addr))

#define MMA16816(c, a, b0_, b1_) \
    asm volatile("mma.sync.aligned.m16n8k16.row.col.f32.bf16.bf16.f32 " \
        "{%0,%1,%2,%3}, {%4,%5,%6,%7}, {%8,%9}, {%0,%1,%2,%3};" \
        : "+f"((c)[0]), "+f"((c)[1]), "+f"((c)[2]), "+f"((c)[3]) \
        : "r"((a)[0]), "r"((a)[1]), "r"((a)[2]), "r"((a)[3]), \
          "r"(b0_), "r"(b1_))

#define MBAR_INIT(a, n) \
    asm volatile("mbarrier.init.shared.b64 [%0], %1;" :: "r"(a), "r"(n) : "memory")
#define MBAR_ARRIVE(a) \
    asm volatile("mbarrier.arrive.shared.b64 _, [%0];" :: "r"(a) : "memory")
#define MBAR_EXPECT_TX(a, bytes) \
    asm volatile("mbarrier.arrive.expect_tx.shared.b64 _, [%0], %1;" \
                 :: "r"(a), "r"(bytes) : "memory")
#define BULK_CP(dst, src, bytes, mbar) \
    asm volatile("cp.async.bulk.shared::cluster.global.mbarrier::complete_tx::bytes " \
                 "[%0], [%1], %2, [%3];" \
                 :: "r"(dst), "l"(src), "r"(bytes), "r"(mbar) : "memory")
#define MBAR_WAIT(a, par) do {                                               \
    uint32_t _m = (a), _p = (par), _d;                                       \
    asm volatile("{\n\t.reg .pred p;\n\t"                                    \
        "mbarrier.try_wait.parity.acquire.cta.shared::cta.b64 p, [%1], %2;\n\t" \
        "selp.b32 %0, 1, 0, p;\n\t}" : "=r"(_d) : "r"(_m), "r"(_p) : "memory"); \
    if (!_d) {                                                               \
        asm volatile("{\n\t.reg .pred P1;\n\tWL%=: \n\t"                     \
            "mbarrier.try_wait.parity.acquire.cta.shared::cta.b64 P1, [%0], %1, 0x989680;\n\t" \
            "@P1 bra.uni WD%=;\n\tbra.uni WL%=;\n\tWD%=: \n\t}"              \
            :: "r"(_m), "r"(_p) : "memory");                                 \
    }                                                                        \
} while (0)

// ---------------------------------------------------------------- small kernels
__global__ void vq_zero() {
    int i = blockIdx.x * 256 + threadIdx.x;   // 36*256 = 9216
    g_counts[i] = 0;
    if (i < 2) g_loss[i] = 0.0;
}

__global__ void vq_e2(const float* __restrict__ Ec, const float* __restrict__ Ef) {
    int gw   = (blockIdx.x * blockDim.x + threadIdx.x) >> 5;
    int lane = threadIdx.x & 31;
    if (gw >= NTOT) return;
    const float* row = (gw < NC) ? (Ec + (size_t)gw * D)
                                 : (Ef + (size_t)(gw - NC) * D);
    const float4* r4 = (const float4*)row;
    float4 a = r4[lane];
    float4 b = r4[lane + 32];
    float s = a.x*a.x + a.y*a.y + a.z*a.z + a.w*a.w
            + b.x*b.x + b.y*b.y + b.z*b.z + b.w*b.w;
    #pragma unroll
    for (int o = 16; o > 0; o >>= 1) s += __shfl_xor_sync(0xffffffffu, s, o);
    if (lane == 0) g_e2[gw] = s;
}

// build padded + K-augmented bf16 embedding matrix (row stride 560B)
__global__ void vq_cvt(const float* __restrict__ Ec, const float* __restrict__ Ef) {
    int idx = blockIdx.x * 256 + threadIdx.x;   // 1260*256 = 322560 = 9216*35
    int row = idx / 35;
    int ch  = idx - row * 35;                   // 16B chunk within 560B row
    uint4 pv = make_uint4(0u, 0u, 0u, 0u);
    if (ch < 32) {
        const float* src = (row < NC) ? (Ec + (size_t)row * D + ch * 8)
                                      : (Ef + (size_t)(row - NC) * D + ch * 8);
        float4 a = ((const float4*)src)[0];
        float4 b = ((const float4*)src)[1];
        pv.x = pk(a.x, a.y); pv.y = pk(a.z, a.w);
        pv.z = pk(b.x, b.y); pv.w = pk(b.z, b.w);
    } else if (ch == 32) {
        pv.x = pk(-0.5f * g_e2[row], 0.f);      // aug col 256 = -e2/2
    }
    *(uint4*)(g_ebf + (size_t)row * SXB + ch * 16) = pv;
}

// ---------------------------------------------------------------- main kernel
__global__ void __launch_bounds__(NTHR, 1) vq_main(
        const float* __restrict__ feats,
        const float* __restrict__ Ec,
        const float* __restrict__ Ef,
        float* __restrict__ out)
{
    extern __shared__ char smc[];
    const uint32_t sbase = smem_u32(smc);
    const int tid  = threadIdx.x;
    const int wid  = tid >> 5;
    const int lane = tid & 31;
    const int wm   = wid & 3;       // warp row group (4 x 32 rows)
    const int wn   = wid >> 2;      // warp col group (4 x 32 embs)
    const int g8   = lane >> 2;     // 0..7
    const int tid4 = lane & 3;

    // role of this CTA
    const float* Xf; int ntiles, gbase_e, valid, gbase, lslot;
    if (blockIdx.x == 0) {
        Xf = feats;                 ntiles = NC / TN;  gbase_e = 0;
        valid = 64;  gbase = 0;     lslot = 0;
    } else {
        int b = blockIdx.x - 1;
        Xf = feats + (size_t)(64 + b * TM) * D;
        ntiles = NF / TN;  gbase_e = NC;
        valid = TM;  gbase = 64 + b * TM;  lslot = 1;
    }

    const uint32_t full0  = sbase + SM_MBAR;
    const uint32_t full1  = sbase + SM_MBAR + 8;
    const uint32_t empty0 = sbase + SM_MBAR + 16;
    const uint32_t empty1 = sbase + SM_MBAR + 24;

    if (tid == 0) {
        MBAR_INIT(full0, 1);  MBAR_INIT(full1, 1);
        MBAR_INIT(empty0, NWARP); MBAR_INIT(empty1, NWARP);
    }

    // convert X block to augmented bf16 smem (pad rows -> 0 data, aug col = 1)
    for (int q = tid; q < TM * 35; q += NTHR) {
        int row = q / 35, ch = q - row * 35;
        uint4 pv = make_uint4(0u, 0u, 0u, 0u);
        if (ch < 32) {
            if (row < valid) {
                const float4* xs = (const float4*)(Xf + (size_t)row * D + ch * 8);
                float4 a = xs[0], b = xs[1];
                pv.x = pk(a.x, a.y); pv.y = pk(a.z, a.w);
                pv.z = pk(b.x, b.y); pv.w = pk(b.z, b.w);
            }
        } else if (ch == 32) {
            pv.x = pk(1.0f, 0.f);                // aug col 256 = 1
        }
        *(uint4*)(smc + SM_X + (size_t)row * SXB + ch * 16) = pv;
    }
    __syncthreads();   // X ready + mbarriers initialized, visible to all

    // prologue: bulk-load tiles 0 and 1
    if (tid == 0) {
        MBAR_EXPECT_TX(full0, TILE_B);
        BULK_CP(sbase + SM_E0, g_ebf + (size_t)gbase_e * SXB, TILE_B, full0);
        MBAR_EXPECT_TX(full1, TILE_B);
        BULK_CP(sbase + SM_E1, g_ebf + (size_t)(gbase_e + TN) * SXB, TILE_B, full1);
    }

    // ldmatrix per-thread offsets
    const int arow  = wm * 32 + (lane & 7) + ((lane >> 3) & 1) * 8;
    const int akoff = (lane >> 4) * 8;
    const uint32_t aoff0 = (uint32_t)(arow * SXB + akoff * 2);
    const uint32_t aoff1 = aoff0 + 16 * SXB;
    const int brow  = (lane & 7) + ((lane >> 4) & 1) * 8;
    const int bkoff = ((lane >> 3) & 1) * 8;
    const uint32_t boff0 = (uint32_t)((wn * 32 + brow) * SXB + bkoff * 2);
    const uint32_t boff1 = boff0 + 16 * SXB;

    // per-thread approx top-3 per owned row (d = -(dot - e2/2), ascending)
    float td[4][3]; int ti[4][3];
    #pragma unroll
    for (int li = 0; li < 4; li++)
        #pragma unroll
        for (int q = 0; q < 3; q++) { td[li][q] = FLT_MAX; ti[li][q] = 0x7fffffff; }

    const uint32_t xb = sbase + SM_X;

    // ---------------- main tile loop (no block-wide syncs) -------------------
    for (int t = 0; t < ntiles; t++) {
        const int bsel = t & 1;
        const uint32_t fullb  = bsel ? full1 : full0;
        const uint32_t emptyb = bsel ? empty1 : empty0;
        MBAR_WAIT(fullb, (uint32_t)((t >> 1) & 1));

        const uint32_t eb = sbase + (bsel ? SM_E1 : SM_E0);

        float acc[2][4][4];
        #pragma unroll
        for (int mt = 0; mt < 2; mt++)
            #pragma unroll
            for (int nt = 0; nt < 4; nt++)
                #pragma unroll
                for (int q = 0; q < 4; q++) acc[mt][nt][q] = 0.f;

        // software-pipelined fragment loop
        uint32_t af[2][2][4], bf[2][2][4];
        LDSM4(af[0][0], xb + aoff0);
        LDSM4(af[0][1], xb + aoff1);
        LDSM4(bf[0][0], eb + boff0);
        LDSM4(bf[0][1], eb + boff1);
        #pragma unroll
        for (int ks = 0; ks < KSTEPS; ks++) {
            const int cur = ks & 1, nxt = cur ^ 1;
            if (ks < KSTEPS - 1) {
                const uint32_t kb = (ks + 1) * 32;
                LDSM4(af[nxt][0], xb + aoff0 + kb);
                LDSM4(af[nxt][1], xb + aoff1 + kb);
                LDSM4(bf[nxt][0], eb + boff0 + kb);
                LDSM4(bf[nxt][1], eb + boff1 + kb);
            }
            #pragma unroll
            for (int np = 0; np < 2; np++) {
                MMA16816(acc[0][2*np],     af[cur][0], bf[cur][np][0], bf[cur][np][1]);
                MMA16816(acc[1][2*np],     af[cur][1], bf[cur][np][0], bf[cur][np][1]);
                MMA16816(acc[0][2*np + 1], af[cur][0], bf[cur][np][2], bf[cur][np][3]);
                MMA16816(acc[1][2*np + 1], af[cur][1], bf[cur][np][2], bf[cur][np][3]);
            }
        }

        // this warp is done reading buffer bsel
        if (lane == 0) MBAR_ARRIVE(emptyb);

        // refill buffer bsel with tile t+2 once all 16 warps released it
        if (t + 2 < ntiles && tid == 0) {
            MBAR_WAIT(emptyb, (uint32_t)((t >> 1) & 1));
            MBAR_EXPECT_TX(fullb, TILE_B);
            BULK_CP(eb, g_ebf + (size_t)(gbase_e + (t + 2) * TN) * SXB,
                    TILE_B, fullb);
        }

        // scores: d = -acc (monotone proxy for e2 - 2*dot); update top-3
        const int ebase = gbase_e + t * TN;
        #pragma unroll
        for (int mt = 0; mt < 2; mt++) {
            #pragma unroll
            for (int nt = 0; nt < 4; nt++) {
                int n  = wn * 32 + nt * 8 + tid4 * 2;
                int ge = ebase + n;
                int l0 = mt * 2, l1 = mt * 2 + 1;
                ins3f(-acc[mt][nt][0], ge,     td[l0][0], ti[l0][0], td[l0][1], ti[l0][1], td[l0][2], ti[l0][2]);
                ins3f(-acc[mt][nt][1], ge + 1, td[l0][0], ti[l0][0], td[l0][1], ti[l0][1], td[l0][2], ti[l0][2]);
                ins3f(-acc[mt][nt][2], ge,     td[l1][0], ti[l1][0], td[l1][1], ti[l1][1], td[l1][2], ti[l1][2]);
                ins3f(-acc[mt][nt][3], ge + 1, td[l1][0], ti[l1][0], td[l1][1], ti[l1][1], td[l1][2], ti[l1][2]);
            }
        }
    }
    __syncthreads();   // all tiles done; smem free for reuse

    // ---------------- merge: 16 threads x top3 -> 48 cands per row -----------
    float* cd  = (float*)smc;                    // [128][48] floats
    int*   ci  = (int*)(smc + 24576);            // [128][48] ints
    float* cd8 = (float*)(smc + 49152);          // [128][8]
    int*   ci8 = (int*)(smc + 53248);            // [128][8]
    int*   sel = (int*)(smc + 57344);            // [128][3]

    const int slot = wn * 4 + tid4;              // 0..15 per row
    #pragma unroll
    for (int li = 0; li < 4; li++) {
        int row = wm * 32 + g8 + li * 8;
        #pragma unroll
        for (int q = 0; q < 3; q++) {
            cd[row * 48 + slot * 3 + q] = td[li][q];
            ci[row * 48 + slot * 3 + q] = ti[li][q];
        }
    }
    __syncthreads();

    // approx top-8 of 48 (selection with tie-break; destructive)
    if (tid < valid) {
        for (int s = 0; s < 8; s++) {
            float bd = FLT_MAX; int bi = 0x7fffffff; int bj = -1;
            for (int j = 0; j < 48; j++) {
                float dv = cd[tid * 48 + j]; int iv = ci[tid * 48 + j];
                if (dlt(dv, iv, bd, bi)) { bd = dv; bi = iv; bj = j; }
            }
            cd[tid * 48 + bj] = FLT_MAX; ci[tid * 48 + bj] = 0x7fffffff;
            cd8[tid * 8 + s] = bd;  ci8[tid * 8 + s] = bi;
        }
    }
    __syncthreads();

    // ---------------- exact fp32 rescore of 8 candidates per row ------------
    for (int it = wid; it < valid * 8; it += NWARP) {
        int row = it >> 3, c = it & 7;
        int idx = ci8[row * 8 + c];
        const float* erow = (idx < NC) ? (Ec + (size_t)idx * D)
                                       : (Ef + (size_t)(idx - NC) * D);
        const float4* e4 = (const float4*)erow;
        const float4* x4 = (const float4*)(Xf + (size_t)row * D);
        float4 ea = e4[lane * 2], ebv = e4[lane * 2 + 1];
        float4 xa = x4[lane * 2], xbv = x4[lane * 2 + 1];
        float dot = ea.x*xa.x + ea.y*xa.y + ea.z*xa.z + ea.w*xa.w
                  + ebv.x*xbv.x + ebv.y*xbv.y + ebv.z*xbv.z + ebv.w*xbv.w;
        #pragma unroll
        for (int o = 16; o > 0; o >>= 1) dot += __shfl_xor_sync(0xffffffffu, dot, o);
        if (lane == 0) cd8[row * 8 + c] = g_e2[idx] - 2.f * dot;
    }
    __syncthreads();

    // exact top-3 with index tie-break (matches lax.top_k stability)
    if (tid < valid) {
        float d0 = FLT_MAX, d1 = FLT_MAX, d2 = FLT_MAX;
        int   i0 = 0x7fffffff, i1 = 0x7fffffff, i2 = 0x7fffffff;
        #pragma unroll
        for (int s = 0; s < 8; s++)
            ins3(cd8[tid * 8 + s], ci8[tid * 8 + s], d0, i0, d1, i1, d2, i2);
        sel[tid * 3 + 0] = i0;
        sel[tid * 3 + 1] = i1;
        sel[tid * 3 + 2] = i2;
    }
    __syncthreads();

    // ---------------- gather + write quantized/indices + loss + counts ------
    float lsum = 0.f;
    for (int j = wid; j < valid * 3; j += NWARP) {
        int r  = j / 3;
        int kk = j - r * 3;
        int idx = sel[j];
        int g  = gbase + r;
        const float* erow = (idx < NC) ? (Ec + (size_t)idx * D)
                                       : (Ef + (size_t)(idx - NC) * D);
        const float4* e4 = (const float4*)erow;
        const float4* x4 = (const float4*)(Xf + (size_t)r * D);
        float4 v0 = e4[lane * 2], v1 = e4[lane * 2 + 1];
        float4 x0 = x4[lane * 2], x1 = x4[lane * 2 + 1];
        size_t qb = QOFF + ((size_t)g * 3 + kk) * D + lane * 8;
        out[qb + 0] = v0.x; out[qb + 1] = v0.y; out[qb + 2] = v0.z; out[qb + 3] = v0.w;
        out[qb + 4] = v1.x; out[qb + 5] = v1.y; out[qb + 6] = v1.z; out[qb + 7] = v1.w;
        float dx;
        dx = v0.x - x0.x; lsum += dx * dx;
        dx = v0.y - x0.y; lsum += dx * dx;
        dx = v0.z - x0.z; lsum += dx * dx;
        dx = v0.w - x0.w; lsum += dx * dx;
        dx = v1.x - x1.x; lsum += dx * dx;
        dx = v1.y - x1.y; lsum += dx * dx;
        dx = v1.z - x1.z; lsum += dx * dx;
        dx = v1.w - x1.w; lsum += dx * dx;
        if (lane == 0) {
            out[ENC_OFF + (size_t)g * 3 + kk] = (float)idx;
            atomicAdd(&g_counts[idx], 1);
        }
    }
    #pragma unroll
    for (int o = 16; o > 0; o >>= 1) lsum += __shfl_xor_sync(0xffffffffu, lsum, o);
    if (lane == 0) atomicAdd(&g_loss[lslot], (double)lsum);
}

// ---------------------------------------------------------------- finalize
__global__ void vq_finalize(float* __restrict__ out) {
    int tid = threadIdx.x;                    // 1024 threads
    float hf = 0.f;
    for (int i = tid; i < NF; i += 1024) {
        float avg = (float)g_counts[NC + i] * (1.0f / 16384.0f);
        hf += avg * logf(avg + 1e-10f);
    }
    float avgc = (float)g_counts[tid] * (1.0f / 64.0f);
    float hc = avgc * logf(avgc + 1e-10f);

    __shared__ float redf[32], redc[32];
    int lane = tid & 31, w = tid >> 5;
    #pragma unroll
    for (int o = 16; o > 0; o >>= 1) {
        hf += __shfl_xor_sync(0xffffffffu, hf, o);
        hc += __shfl_xor_sync(0xffffffffu, hc, o);
    }
    if (lane == 0) { redf[w] = hf; redc[w] = hc; }
    __syncthreads();
    if (tid < 32) {
        float f = redf[tid], c = redc[tid];
        #pragma unroll
        for (int o = 16; o > 0; o >>= 1) {
            f += __shfl_xor_sync(0xffffffffu, f, o);
            c += __shfl_xor_sync(0xffffffffu, c, o);
        }
        if (tid == 0) {
            out[FPERP_OFF] = expf(-f);
            out[CPERP_OFF] = expf(-c);
            out[0] = (float)(1.25 * (g_loss[0] / (64.0 * 3.0 * 256.0)
                                   + g_loss[1] / (16384.0 * 3.0 * 256.0)));
        }
    }
}

// ---------------------------------------------------------------- launcher
extern "C" void kernel_launch(void* const* d_in, const int* in_sizes, int n_in,
                              void* d_out, int out_size) {
    (void)in_sizes; (void)n_in; (void)out_size;
    const float* feats = (const float*)d_in[0];
    const float* Ec    = (const float*)d_in[1];
    const float* Ef    = (const float*)d_in[2];
    float* out = (float*)d_out;

    cudaFuncSetAttribute(vq_main, cudaFuncAttributeMaxDynamicSharedMemorySize, SM_TOTAL);

    vq_zero<<<36, 256>>>();
    vq_e2<<<NTOT / 8, 256>>>(Ec, Ef);
    vq_cvt<<<1260, 256>>>(Ec, Ef);
    vq_main<<<129, NTHR, SM_TOTAL>>>(feats, Ec, Ef, out);
    vq_finalize<<<1, 1024>>>(out);
}